// round 14
// baseline (speedup 1.0000x reference)
#include <cuda_runtime.h>
#include <cuda_fp16.h>

// ---------------- problem constants ----------------
#define BATCH 8
#define NTOK  4096
#define CCH   768
#define NHEAD 12
#define HDIM  64
#define NWIN  16
#define WTOK  256
#define K_DIM 768
#define SCALE 0.125f
#define MTOT  (BATCH * NTOK)     // 32768
#define PL3   (BATCH * NWIN * NHEAD * WTOK * HDIM)   // 25,165,824

typedef unsigned long long ull;
typedef unsigned int u32;

// ---------------- device scratch (fp16 planes) ----------------
__device__ __half g_q[PL3];                  // Q, SCALE pre-folded, single fp16
__device__ __half g_kh[PL3], g_kl[PL3];      // K hi/lo
__device__ __half g_vh[PL3], g_vl[PL3];      // V hi/lo
__device__ __half g_x[(size_t)MTOT * K_DIM]; // permuted x, single fp16
__device__ __half g_y[(size_t)MTOT * K_DIM]; // attn out (orig order), single fp16
__device__ __half g_wqh[2304 * 768], g_wql[2304 * 768];
__device__ __half g_wph[768 * 768],  g_wpl[768 * 768];

// ---------------- helpers ----------------
__device__ __forceinline__ int perm_tok(int p) {
    int wnd = p >> 8, r = p & 255;
    int wr = wnd >> 2, wc = wnd & 3;
    int i = r >> 4, j = r & 15;
    return ((wr << 4) + i) * 64 + (wc << 4) + j;
}
__device__ __forceinline__ u32 smem_u32(const void* p) {
    u32 a;
    asm("{ .reg .u64 t; cvta.to.shared.u64 t, %1; cvt.u32.u64 %0, t; }" : "=r"(a) : "l"(p));
    return a;
}
__device__ __forceinline__ void ldsm4(u32& r0, u32& r1, u32& r2, u32& r3, u32 addr) {
    asm volatile("ldmatrix.sync.aligned.m8n8.x4.shared.b16 {%0,%1,%2,%3}, [%4];"
                 : "=r"(r0), "=r"(r1), "=r"(r2), "=r"(r3) : "r"(addr));
}
__device__ __forceinline__ void ldsm4t(u32& r0, u32& r1, u32& r2, u32& r3, u32 addr) {
    asm volatile("ldmatrix.sync.aligned.m8n8.x4.trans.shared.b16 {%0,%1,%2,%3}, [%4];"
                 : "=r"(r0), "=r"(r1), "=r"(r2), "=r"(r3) : "r"(addr));
}
// fp32-accumulator HMMA
__device__ __forceinline__ void mma16816h(float* c, const u32* a, const u32* b) {
    asm volatile("mma.sync.aligned.m16n8k16.row.col.f32.f16.f16.f32 "
                 "{%0,%1,%2,%3}, {%4,%5,%6,%7}, {%8,%9}, {%0,%1,%2,%3};"
                 : "+f"(c[0]), "+f"(c[1]), "+f"(c[2]), "+f"(c[3])
                 : "r"(a[0]), "r"(a[1]), "r"(a[2]), "r"(a[3]), "r"(b[0]), "r"(b[1]));
}
// fp16-accumulator HMMA (for small lo-correction terms)
__device__ __forceinline__ void mma16816hh(u32* c, const u32* a, const u32* b) {
    asm volatile("mma.sync.aligned.m16n8k16.row.col.f16.f16.f16.f16 "
                 "{%0,%1}, {%2,%3,%4,%5}, {%6,%7}, {%0,%1};"
                 : "+r"(c[0]), "+r"(c[1])
                 : "r"(a[0]), "r"(a[1]), "r"(a[2]), "r"(a[3]), "r"(b[0]), "r"(b[1]));
}
__device__ __forceinline__ void cpasync16(u32 saddr, const void* g) {
    asm volatile("cp.async.cg.shared.global [%0], [%1], 16;" :: "r"(saddr), "l"(g) : "memory");
}
#define CP_COMMIT()  asm volatile("cp.async.commit_group;" ::: "memory")
#define CP_WAIT(n)   asm volatile("cp.async.wait_group %0;" :: "n"(n) : "memory")

// pack two f32 -> f16x2 (element0 = x0)
__device__ __forceinline__ u32 pkh2(float x0, float x1) {
    u32 r;
    asm("cvt.rn.f16x2.f32 %0, %2, %1;" : "=r"(r) : "f"(x0), "f"(x1));
    return r;
}
__device__ __forceinline__ float2 uph2(u32 v) {
    __half2 h = *(__half2*)&v;
    return __half22float2(h);
}

// ---------------- convert kernels ----------------
__global__ __launch_bounds__(192) void convert_x(const float* __restrict__ x)
{
    const int m = blockIdx.x;
    const int t = threadIdx.x;
    const int b = m >> 12, p = m & 4095;
    const float4* src = (const float4*)(x + (size_t)((b << 12) + perm_tok(p)) * K_DIM);
    float4 v = src[t];
    ull packed = (ull)pkh2(v.x, v.y) | ((ull)pkh2(v.z, v.w) << 32);
    *(ull*)&g_x[(size_t)m * K_DIM + t * 4] = packed;
}

__global__ __launch_bounds__(192) void convert_w(const float* __restrict__ qkv_w,
                                                 const float* __restrict__ proj_w)
{
    const int row = blockIdx.x;
    const int t = threadIdx.x;
    const float* src;
    __half *dh, *dl;
    if (row < 2304) {
        src = qkv_w + (size_t)row * 768;
        dh = g_wqh + (size_t)row * 768; dl = g_wql + (size_t)row * 768;
    } else {
        int r2 = row - 2304;
        src = proj_w + (size_t)r2 * 768;
        dh = g_wph + (size_t)r2 * 768; dl = g_wpl + (size_t)r2 * 768;
    }
    float4 v = ((const float4*)src)[t];
    float h0 = __half2float(__float2half(v.x));
    float h1 = __half2float(__float2half(v.y));
    float h2 = __half2float(__float2half(v.z));
    float h3 = __half2float(__float2half(v.w));
    *(ull*)&dh[t * 4] = (ull)pkh2(h0, h1) | ((ull)pkh2(h2, h3) << 32);
    *(ull*)&dl[t * 4] = (ull)pkh2(v.x - h0, v.y - h1) | ((ull)pkh2(v.z - h2, v.w - h3) << 32);
}

// ---------------- mma.sync fp16 asymmetric 2-term GEMM ----------------
// C = A*Wh (f32 accum) + A*Wl (f16 accum — lo term is ~2^-12 smaller, fp16 accum is safe)
// CTA 128x192, BK=32, 12 warps (4x3), warp tile 32x64, double-buffered cp.async.
#define GM_SMEM 81920

template <int MODE>
__global__ __launch_bounds__(384, 1)
void gemm_mma(const float* __restrict__ bias, float* __restrict__ Cout)
{
    extern __shared__ char smem[];
    const __half* Ap0 = (MODE == 0) ? g_x : g_y;
    const __half* Wh0 = (MODE == 0) ? g_wqh : g_wph;
    const __half* Wl0 = (MODE == 0) ? g_wql : g_wpl;

    const int tid = threadIdx.x;
    const int lane = tid & 31, wid = tid >> 5;
    const int wyy = wid / 3, wx = wid - wyy * 3;   // 4x3 warp grid
    const int m0 = blockIdx.y * 128;
    const int n0 = blockIdx.x * 192;
    const u32 sb = smem_u32(smem);

    const __half* Ahp = Ap0 + (size_t)m0 * 768;
    const __half* Whp = Wh0 + (size_t)n0 * 768;
    const __half* Wlp = Wl0 + (size_t)n0 * 768;

    float acc[2][8][4];
    u32 accl[2][8][2];
#pragma unroll
    for (int mt = 0; mt < 2; mt++)
#pragma unroll
        for (int nt = 0; nt < 8; nt++) {
#pragma unroll
            for (int j = 0; j < 4; j++) acc[mt][nt][j] = 0.f;
            accl[mt][nt][0] = 0u; accl[mt][nt][1] = 0u;
        }

    const u32 aOff = (u32)((wyy * 32 + (lane & 15)) * 80 + ((lane >> 4) * 16));
    const u32 bOff = (u32)((wx * 64 + ((lane >> 4) << 3) + (lane & 7)) * 80
                           + (((lane >> 3) & 1) * 16));

#define LOAD_TILE(c, buf) do {                                                    \
    u32 dbase = sb + (u32)(buf) * 40960u;                                         \
    int kk = (c) * 32;                                                            \
    _Pragma("unroll")                                                             \
    for (int i = 0; i < 6; i++) {                                                 \
        int idx = tid + i * 384;                                                  \
        if (idx < 512) {                                                          \
            int row = idx >> 2, q = idx & 3;                                      \
            cpasync16(dbase + (u32)(row * 80 + q * 16),                           \
                      Ahp + (size_t)row * 768 + kk + q * 8);                      \
        } else if (idx < 1280) {                                                  \
            int j2 = idx - 512; int row = j2 >> 2, q = j2 & 3;                    \
            cpasync16(dbase + 10240u + (u32)(row * 80 + q * 16),                  \
                      Whp + (size_t)row * 768 + kk + q * 8);                      \
        } else if (idx < 2048) {                                                  \
            int j2 = idx - 1280; int row = j2 >> 2, q = j2 & 3;                   \
            cpasync16(dbase + 25600u + (u32)(row * 80 + q * 16),                  \
                      Wlp + (size_t)row * 768 + kk + q * 8);                      \
        }                                                                         \
    }                                                                             \
} while (0)

    LOAD_TILE(0, 0);
    CP_COMMIT();

    for (int c = 0; c < 24; c++) {
        const int buf = c & 1;
        if (c + 1 < 24) {
            LOAD_TILE(c + 1, buf ^ 1);
            CP_COMMIT();
            CP_WAIT(1);
        } else {
            CP_WAIT(0);
        }
        __syncthreads();

        const u32 base = sb + (u32)buf * 40960u;
#pragma unroll
        for (int ks = 0; ks < 2; ks++) {
            const u32 kb = (u32)(ks * 32);
            u32 a[2][4], bh[8][2], bl[8][2];
#pragma unroll
            for (int mt = 0; mt < 2; mt++) {
                u32 ad = base + aOff + (u32)(mt * 16 * 80) + kb;
                ldsm4(a[mt][0], a[mt][1], a[mt][2], a[mt][3], ad);
            }
#pragma unroll
            for (int p = 0; p < 4; p++) {
                u32 bd = base + 10240u + bOff + (u32)(p * 16 * 80) + kb;
                u32 r0, r1, r2, r3;
                ldsm4(r0, r1, r2, r3, bd);
                bh[2 * p][0] = r0; bh[2 * p][1] = r1;
                bh[2 * p + 1][0] = r2; bh[2 * p + 1][1] = r3;
                ldsm4(r0, r1, r2, r3, bd + 15360u);
                bl[2 * p][0] = r0; bl[2 * p][1] = r1;
                bl[2 * p + 1][0] = r2; bl[2 * p + 1][1] = r3;
            }
#pragma unroll
            for (int mt = 0; mt < 2; mt++)
#pragma unroll
                for (int nt = 0; nt < 8; nt++) {
                    mma16816h(acc[mt][nt], a[mt], bh[nt]);
                    mma16816hh(accl[mt][nt], a[mt], bl[nt]);
                }
        }
        __syncthreads();
    }

    // ---- epilogue (merge fp16 lo accumulators) ----
    const int tsel = (MODE == 0) ? (n0 / 768) : 0;
#pragma unroll
    for (int mt = 0; mt < 2; mt++) {
        const int m_g = m0 + wyy * 32 + mt * 16 + (lane >> 2);
        if (MODE == 0) {
            const int bq = m_g >> 12, ptok = m_g & 4095;
            const int wnd = ptok >> 8, rr = ptok & 255;
#pragma unroll
            for (int nt = 0; nt < 8; nt++) {
                const int ncol = n0 + wx * 64 + nt * 8;
                const int rem = ncol - tsel * 768;
                const int h = rem >> 6;
                const int d = (rem & 63) + 2 * (lane & 3);
                size_t rowbase = (((size_t)bq * 16 + wnd) * 12 + h) * 256;
                size_t i0 = (rowbase + rr) * 64 + d;
                size_t i1 = (rowbase + rr + 8) * 64 + d;
                float2 l01 = uph2(accl[mt][nt][0]);
                float2 l23 = uph2(accl[mt][nt][1]);
                float v0 = acc[mt][nt][0] + l01.x, v1 = acc[mt][nt][1] + l01.y;
                float v2 = acc[mt][nt][2] + l23.x, v3 = acc[mt][nt][3] + l23.y;
                if (tsel == 0) {
                    *(u32*)&g_q[i0] = pkh2(v0 * SCALE, v1 * SCALE);
                    *(u32*)&g_q[i1] = pkh2(v2 * SCALE, v3 * SCALE);
                } else {
                    __half* ph = (tsel == 1) ? g_kh : g_vh;
                    __half* pl = (tsel == 1) ? g_kl : g_vl;
                    float h0 = __half2float(__float2half(v0));
                    float h1 = __half2float(__float2half(v1));
                    float h2 = __half2float(__float2half(v2));
                    float h3 = __half2float(__float2half(v3));
                    *(u32*)&ph[i0] = pkh2(h0, h1);
                    *(u32*)&pl[i0] = pkh2(v0 - h0, v1 - h1);
                    *(u32*)&ph[i1] = pkh2(h2, h3);
                    *(u32*)&pl[i1] = pkh2(v2 - h2, v3 - h3);
                }
            }
        } else {
#pragma unroll
            for (int nt = 0; nt < 8; nt++) {
                const int ncol = n0 + wx * 64 + nt * 8 + 2 * (lane & 3);
                const float b0 = bias[ncol], b1 = bias[ncol + 1];
                float2 l01 = uph2(accl[mt][nt][0]);
                float2 l23 = uph2(accl[mt][nt][1]);
                *(float2*)(Cout + (size_t)m_g * 768 + ncol) =
                    make_float2(acc[mt][nt][0] + l01.x + b0, acc[mt][nt][1] + l01.y + b1);
                *(float2*)(Cout + (size_t)(m_g + 8) * 768 + ncol) =
                    make_float2(acc[mt][nt][2] + l23.x + b0, acc[mt][nt][3] + l23.y + b1);
            }
        }
    }
#undef LOAD_TILE
}

// ---------------- flash attention, fp16 2-term (lo terms on fp16 accum) ----------------
#define AT_PL   36864
#define AT_SMEM (5 * AT_PL)      // 184320

__global__ __launch_bounds__(256, 1)
void attn_mma()
{
    extern __shared__ char smem[];
    const u32 sb = smem_u32(smem);

    const int tid = threadIdx.x;
    const int lane = tid & 31, wid = tid >> 5;
    const int blk = blockIdx.x;
    const int h = blk % NHEAD;
    const int t2 = blk / NHEAD;
    const int wnd = t2 % NWIN;
    const int b = t2 / NWIN;

    // ---- load 5 planes into padded smem ----
    {
        const size_t blkoff = (((size_t)b * NWIN + wnd) * NHEAD + h) * (WTOK * HDIM);
        const __half* srcs[5] = {g_q + blkoff, g_kh + blkoff, g_kl + blkoff,
                                 g_vh + blkoff, g_vl + blkoff};
#pragma unroll
        for (int p5 = 0; p5 < 5; p5++) {
            const __half* src = srcs[p5];
#pragma unroll
            for (int i = 0; i < 8; i++) {
                int seg = i * 256 + tid;          // 0..2047
                int row = seg >> 3, sc = seg & 7;
                uint4 v = ((const uint4*)(src + row * 64))[sc];
                *(uint4*)(smem + (size_t)p5 * AT_PL + row * 144 + sc * 16) = v;
            }
        }
    }
    __syncthreads();

    float out[2][8][4];
#pragma unroll
    for (int mt = 0; mt < 2; mt++)
#pragma unroll
        for (int nt = 0; nt < 8; nt++)
#pragma unroll
            for (int j = 0; j < 4; j++) out[mt][nt][j] = 0.f;
    float mrun[2][2] = {{-1e30f, -1e30f}, {-1e30f, -1e30f}};
    float lrun[2][2] = {{0.f, 0.f}, {0.f, 0.f}};

    const u32 qrow_base = (u32)(wid * 32 + (lane & 15));
    const u32 qcol = (u32)((lane >> 4) * 16);
    const u32 krow_off = (u32)(((lane >> 4) << 3) + (lane & 7));
    const u32 kcol = (u32)(((lane >> 3) & 1) * 16);
    const u32 vrow_off = (u32)(lane & 15);
    const u32 vcol = (u32)((lane >> 4) * 16);

    for (int jc = 0; jc < 4; jc++) {
        // ---- S = Q*Kh' (f32) + Q*Kl' (f16 accum) ----
        float s[2][8][4];
        u32 sl[2][8][2];
#pragma unroll
        for (int mt = 0; mt < 2; mt++)
#pragma unroll
            for (int nt = 0; nt < 8; nt++) {
#pragma unroll
                for (int j = 0; j < 4; j++) s[mt][nt][j] = 0.f;
                sl[mt][nt][0] = 0u; sl[mt][nt][1] = 0u;
            }

#pragma unroll
        for (int ks = 0; ks < 4; ks++) {
            u32 qa[2][4];
#pragma unroll
            for (int mt = 0; mt < 2; mt++) {
                u32 ad = sb + (qrow_base + mt * 16) * 144 + qcol + ks * 32;
                ldsm4(qa[mt][0], qa[mt][1], qa[mt][2], qa[mt][3], ad);
            }
            u32 kh[8][2], kl[8][2];
#pragma unroll
            for (int p = 0; p < 4; p++) {
                u32 row = (u32)(jc * 64 + p * 16) + krow_off;
                u32 bd = sb + AT_PL + row * 144 + kcol + ks * 32;
                u32 r0, r1, r2, r3;
                ldsm4(r0, r1, r2, r3, bd);
                kh[2 * p][0] = r0; kh[2 * p][1] = r1;
                kh[2 * p + 1][0] = r2; kh[2 * p + 1][1] = r3;
                ldsm4(r0, r1, r2, r3, bd + AT_PL);
                kl[2 * p][0] = r0; kl[2 * p][1] = r1;
                kl[2 * p + 1][0] = r2; kl[2 * p + 1][1] = r3;
            }
#pragma unroll
            for (int mt = 0; mt < 2; mt++)
#pragma unroll
                for (int nt = 0; nt < 8; nt++) {
                    mma16816h(s[mt][nt], qa[mt], kh[nt]);
                    mma16816hh(sl[mt][nt], qa[mt], kl[nt]);
                }
        }
        // merge lo into s
#pragma unroll
        for (int mt = 0; mt < 2; mt++)
#pragma unroll
            for (int nt = 0; nt < 8; nt++) {
                float2 l01 = uph2(sl[mt][nt][0]);
                float2 l23 = uph2(sl[mt][nt][1]);
                s[mt][nt][0] += l01.x; s[mt][nt][1] += l01.y;
                s[mt][nt][2] += l23.x; s[mt][nt][3] += l23.y;
            }

        // ---- online softmax ----
#pragma unroll
        for (int mt = 0; mt < 2; mt++) {
            float mx0 = -1e30f, mx1 = -1e30f;
#pragma unroll
            for (int nt = 0; nt < 8; nt++) {
                mx0 = fmaxf(mx0, fmaxf(s[mt][nt][0], s[mt][nt][1]));
                mx1 = fmaxf(mx1, fmaxf(s[mt][nt][2], s[mt][nt][3]));
            }
            mx0 = fmaxf(mx0, __shfl_xor_sync(0xffffffffu, mx0, 1));
            mx0 = fmaxf(mx0, __shfl_xor_sync(0xffffffffu, mx0, 2));
            mx1 = fmaxf(mx1, __shfl_xor_sync(0xffffffffu, mx1, 1));
            mx1 = fmaxf(mx1, __shfl_xor_sync(0xffffffffu, mx1, 2));
            const float mn0 = fmaxf(mrun[mt][0], mx0);
            const float mn1 = fmaxf(mrun[mt][1], mx1);
            const float c0 = __expf(mrun[mt][0] - mn0);
            const float c1 = __expf(mrun[mt][1] - mn1);
            mrun[mt][0] = mn0; mrun[mt][1] = mn1;
            lrun[mt][0] *= c0; lrun[mt][1] *= c1;
#pragma unroll
            for (int nt = 0; nt < 8; nt++) {
                out[mt][nt][0] *= c0; out[mt][nt][1] *= c0;
                out[mt][nt][2] *= c1; out[mt][nt][3] *= c1;
            }
            float sum0 = 0.f, sum1 = 0.f;
#pragma unroll
            for (int nt = 0; nt < 8; nt++) {
                float p0 = __expf(s[mt][nt][0] - mn0);
                float p1 = __expf(s[mt][nt][1] - mn0);
                float p2 = __expf(s[mt][nt][2] - mn1);
                float p3 = __expf(s[mt][nt][3] - mn1);
                s[mt][nt][0] = p0; s[mt][nt][1] = p1;
                s[mt][nt][2] = p2; s[mt][nt][3] = p3;
                sum0 += p0 + p1; sum1 += p2 + p3;
            }
            sum0 += __shfl_xor_sync(0xffffffffu, sum0, 1);
            sum0 += __shfl_xor_sync(0xffffffffu, sum0, 2);
            sum1 += __shfl_xor_sync(0xffffffffu, sum1, 1);
            sum1 += __shfl_xor_sync(0xffffffffu, sum1, 2);
            lrun[mt][0] += sum0; lrun[mt][1] += sum1;
        }

        // ---- O += P*Vh (f32) + P*Vl (f16 accum, merged per-jc) ----
        u32 outl[2][8][2];
#pragma unroll
        for (int mt = 0; mt < 2; mt++)
#pragma unroll
            for (int nt = 0; nt < 8; nt++) { outl[mt][nt][0] = 0u; outl[mt][nt][1] = 0u; }

#pragma unroll
        for (int ks = 0; ks < 4; ks++) {
            u32 pa[2][4];
#pragma unroll
            for (int mt = 0; mt < 2; mt++) {
#pragma unroll
                for (int half = 0; half < 2; half++) {
                    const float* sv = s[mt][2 * ks + half];
                    pa[mt][0 + 2 * half] = pkh2(sv[0], sv[1]);
                    pa[mt][1 + 2 * half] = pkh2(sv[2], sv[3]);
                }
            }
            u32 vh[8][2], vl[8][2];
#pragma unroll
            for (int p = 0; p < 4; p++) {
                u32 row = (u32)(jc * 64 + ks * 16) + vrow_off;
                u32 vd = sb + 3 * AT_PL + row * 144 + vcol + p * 32;
                u32 r0, r1, r2, r3;
                ldsm4t(r0, r1, r2, r3, vd);
                vh[2 * p][0] = r0; vh[2 * p][1] = r1;
                vh[2 * p + 1][0] = r2; vh[2 * p + 1][1] = r3;
                ldsm4t(r0, r1, r2, r3, vd + AT_PL);
                vl[2 * p][0] = r0; vl[2 * p][1] = r1;
                vl[2 * p + 1][0] = r2; vl[2 * p + 1][1] = r3;
            }
#pragma unroll
            for (int mt = 0; mt < 2; mt++)
#pragma unroll
                for (int nt = 0; nt < 8; nt++) {
                    mma16816h(out[mt][nt], pa[mt], vh[nt]);
                    mma16816hh(outl[mt][nt], pa[mt], vl[nt]);
                }
        }
        // merge lo into out (after rescale, before next iteration's rescale)
#pragma unroll
        for (int mt = 0; mt < 2; mt++)
#pragma unroll
            for (int nt = 0; nt < 8; nt++) {
                float2 l01 = uph2(outl[mt][nt][0]);
                float2 l23 = uph2(outl[mt][nt][1]);
                out[mt][nt][0] += l01.x; out[mt][nt][1] += l01.y;
                out[mt][nt][2] += l23.x; out[mt][nt][3] += l23.y;
            }
    }

    // ---- epilogue: scale by 1/l, inverse-perm scatter, write y single fp16 ----
#pragma unroll
    for (int mt = 0; mt < 2; mt++) {
        const float inv0 = 1.f / lrun[mt][0];
        const float inv1 = 1.f / lrun[mt][1];
#pragma unroll
        for (int half = 0; half < 2; half++) {
            const int row = wid * 32 + mt * 16 + (lane >> 2) + half * 8;
            const int n = perm_tok(wnd * WTOK + row);
            const size_t base = ((size_t)(b * NTOK + n)) * CCH + h * HDIM;
            const float inv = half ? inv1 : inv0;
#pragma unroll
            for (int nt = 0; nt < 8; nt++) {
                const int col = nt * 8 + 2 * (lane & 3);
                float v0 = out[mt][nt][2 * half] * inv;
                float v1 = out[mt][nt][2 * half + 1] * inv;
                *(u32*)&g_y[base + col] = pkh2(v0, v1);
            }
        }
    }
}

// ---------------- launch ----------------
extern "C" void kernel_launch(void* const* d_in, const int* in_sizes, int n_in,
                              void* d_out, int out_size)
{
    const float* x      = (const float*)d_in[0];
    const float* qkv_w  = (const float*)d_in[1];
    const float* proj_w = (const float*)d_in[2];
    const float* proj_b = (const float*)d_in[3];
    float* out = (float*)d_out;

    cudaFuncSetAttribute(attn_mma, cudaFuncAttributeMaxDynamicSharedMemorySize, AT_SMEM);
    cudaFuncSetAttribute(gemm_mma<0>, cudaFuncAttributeMaxDynamicSharedMemorySize, GM_SMEM);
    cudaFuncSetAttribute(gemm_mma<1>, cudaFuncAttributeMaxDynamicSharedMemorySize, GM_SMEM);

    convert_x<<<MTOT, 192>>>(x);
    convert_w<<<3072, 192>>>(qkv_w, proj_w);

    // QKV: M=32768 x N=2304 -> (12, 256)
    gemm_mma<0><<<dim3(12, 256), 384, GM_SMEM>>>(nullptr, nullptr);

    attn_mma<<<BATCH * NWIN * NHEAD, 256, AT_SMEM>>>();

    // proj: M=32768 x N=768 -> (4, 256)
    gemm_mma<1><<<dim3(4, 256), 384, GM_SMEM>>>(proj_b, out);
}

// round 15
// speedup vs baseline: 1.4097x; 1.4097x over previous
#include <cuda_runtime.h>
#include <cuda_fp16.h>

// ---------------- problem constants ----------------
#define BATCH 8
#define NTOK  4096
#define CCH   768
#define NHEAD 12
#define HDIM  64
#define NWIN  16
#define WTOK  256
#define K_DIM 768
#define SCALE 0.125f
#define MTOT  (BATCH * NTOK)     // 32768
#define PL3   (BATCH * NWIN * NHEAD * WTOK * HDIM)   // 25,165,824

typedef unsigned long long ull;
typedef unsigned int u32;

// ---------------- device scratch (fp16 planes) ----------------
__device__ __half g_q[PL3];                  // Q, SCALE pre-folded, single fp16
__device__ __half g_kh[PL3], g_kl[PL3];      // K hi/lo
__device__ __half g_vh[PL3], g_vl[PL3];      // V hi/lo
__device__ __half g_x[(size_t)MTOT * K_DIM]; // permuted x, single fp16
__device__ __half g_y[(size_t)MTOT * K_DIM]; // attn out (orig order), single fp16
__device__ __half g_wq[2304 * 768];          // qkv weights, single fp16
__device__ __half g_wp[768 * 768];           // proj weights, single fp16

// ---------------- helpers ----------------
__device__ __forceinline__ int perm_tok(int p) {
    int wnd = p >> 8, r = p & 255;
    int wr = wnd >> 2, wc = wnd & 3;
    int i = r >> 4, j = r & 15;
    return ((wr << 4) + i) * 64 + (wc << 4) + j;
}
__device__ __forceinline__ u32 smem_u32(const void* p) {
    u32 a;
    asm("{ .reg .u64 t; cvta.to.shared.u64 t, %1; cvt.u32.u64 %0, t; }" : "=r"(a) : "l"(p));
    return a;
}
__device__ __forceinline__ void ldsm4(u32& r0, u32& r1, u32& r2, u32& r3, u32 addr) {
    asm volatile("ldmatrix.sync.aligned.m8n8.x4.shared.b16 {%0,%1,%2,%3}, [%4];"
                 : "=r"(r0), "=r"(r1), "=r"(r2), "=r"(r3) : "r"(addr));
}
__device__ __forceinline__ void ldsm4t(u32& r0, u32& r1, u32& r2, u32& r3, u32 addr) {
    asm volatile("ldmatrix.sync.aligned.m8n8.x4.trans.shared.b16 {%0,%1,%2,%3}, [%4];"
                 : "=r"(r0), "=r"(r1), "=r"(r2), "=r"(r3) : "r"(addr));
}
__device__ __forceinline__ void mma16816h(float* c, const u32* a, const u32* b) {
    asm volatile("mma.sync.aligned.m16n8k16.row.col.f32.f16.f16.f32 "
                 "{%0,%1,%2,%3}, {%4,%5,%6,%7}, {%8,%9}, {%0,%1,%2,%3};"
                 : "+f"(c[0]), "+f"(c[1]), "+f"(c[2]), "+f"(c[3])
                 : "r"(a[0]), "r"(a[1]), "r"(a[2]), "r"(a[3]), "r"(b[0]), "r"(b[1]));
}
__device__ __forceinline__ void cpasync16(u32 saddr, const void* g) {
    asm volatile("cp.async.cg.shared.global [%0], [%1], 16;" :: "r"(saddr), "l"(g) : "memory");
}
#define CP_COMMIT()  asm volatile("cp.async.commit_group;" ::: "memory")
#define CP_WAIT(n)   asm volatile("cp.async.wait_group %0;" :: "n"(n) : "memory")

// pack two f32 -> f16x2 (element0 = x0)
__device__ __forceinline__ u32 pkh2(float x0, float x1) {
    u32 r;
    asm("cvt.rn.f16x2.f32 %0, %2, %1;" : "=r"(r) : "f"(x0), "f"(x1));
    return r;
}

// ---------------- convert kernels ----------------
__global__ __launch_bounds__(192) void convert_x(const float* __restrict__ x)
{
    const int m = blockIdx.x;
    const int t = threadIdx.x;
    const int b = m >> 12, p = m & 4095;
    const float4* src = (const float4*)(x + (size_t)((b << 12) + perm_tok(p)) * K_DIM);
    float4 v = src[t];
    ull packed = (ull)pkh2(v.x, v.y) | ((ull)pkh2(v.z, v.w) << 32);
    *(ull*)&g_x[(size_t)m * K_DIM + t * 4] = packed;
}

__global__ __launch_bounds__(192) void convert_w(const float* __restrict__ qkv_w,
                                                 const float* __restrict__ proj_w)
{
    const int row = blockIdx.x;
    const int t = threadIdx.x;
    const float* src;
    __half* dh;
    if (row < 2304) {
        src = qkv_w + (size_t)row * 768;
        dh = g_wq + (size_t)row * 768;
    } else {
        int r2 = row - 2304;
        src = proj_w + (size_t)r2 * 768;
        dh = g_wp + (size_t)r2 * 768;
    }
    float4 v = ((const float4*)src)[t];
    *(ull*)&dh[t * 4] = (ull)pkh2(v.x, v.y) | ((ull)pkh2(v.z, v.w) << 32);
}

// ---------------- mma.sync fp16 single-term GEMM ----------------
// C[m][n] = sum_k A[m][k]*W[n][k], both single fp16, fp32 accum.
// CTA 128x192, BK=32, 12 warps (4x3), warp tile 32x64, double-buffered cp.async.
// smem/buf: A 10240 | W 15360 = 25600; x2 = 51200.
#define GM_SMEM 51200

template <int MODE>
__global__ __launch_bounds__(384, 1)
void gemm_mma(const float* __restrict__ bias, float* __restrict__ Cout)
{
    extern __shared__ char smem[];
    const __half* Ap0 = (MODE == 0) ? g_x : g_y;
    const __half* Wp0 = (MODE == 0) ? g_wq : g_wp;

    const int tid = threadIdx.x;
    const int lane = tid & 31, wid = tid >> 5;
    const int wyy = wid / 3, wx = wid - wyy * 3;   // 4x3 warp grid
    const int m0 = blockIdx.y * 128;
    const int n0 = blockIdx.x * 192;
    const u32 sb = smem_u32(smem);

    const __half* Ahp = Ap0 + (size_t)m0 * 768;
    const __half* Whp = Wp0 + (size_t)n0 * 768;

    float acc[2][8][4];
#pragma unroll
    for (int mt = 0; mt < 2; mt++)
#pragma unroll
        for (int nt = 0; nt < 8; nt++)
#pragma unroll
            for (int j = 0; j < 4; j++) acc[mt][nt][j] = 0.f;

    const u32 aOff = (u32)((wyy * 32 + (lane & 15)) * 80 + ((lane >> 4) * 16));
    const u32 bOff = (u32)((wx * 64 + ((lane >> 4) << 3) + (lane & 7)) * 80
                           + (((lane >> 3) & 1) * 16));

    // loader: 1280 16B segments (A:512, W:768)
#define LOAD_TILE(c, buf) do {                                                    \
    u32 dbase = sb + (u32)(buf) * 25600u;                                         \
    int kk = (c) * 32;                                                            \
    _Pragma("unroll")                                                             \
    for (int i = 0; i < 4; i++) {                                                 \
        int idx = tid + i * 384;                                                  \
        if (idx < 512) {                                                          \
            int row = idx >> 2, q = idx & 3;                                      \
            cpasync16(dbase + (u32)(row * 80 + q * 16),                           \
                      Ahp + (size_t)row * 768 + kk + q * 8);                      \
        } else if (idx < 1280) {                                                  \
            int j2 = idx - 512; int row = j2 >> 2, q = j2 & 3;                    \
            cpasync16(dbase + 10240u + (u32)(row * 80 + q * 16),                  \
                      Whp + (size_t)row * 768 + kk + q * 8);                      \
        }                                                                         \
    }                                                                             \
} while (0)

    LOAD_TILE(0, 0);
    CP_COMMIT();

    for (int c = 0; c < 24; c++) {
        const int buf = c & 1;
        if (c + 1 < 24) {
            LOAD_TILE(c + 1, buf ^ 1);
            CP_COMMIT();
            CP_WAIT(1);
        } else {
            CP_WAIT(0);
        }
        __syncthreads();

        const u32 base = sb + (u32)buf * 25600u;
#pragma unroll
        for (int ks = 0; ks < 2; ks++) {
            const u32 kb = (u32)(ks * 32);
            u32 a[2][4], bw[8][2];
#pragma unroll
            for (int mt = 0; mt < 2; mt++) {
                u32 ad = base + aOff + (u32)(mt * 16 * 80) + kb;
                ldsm4(a[mt][0], a[mt][1], a[mt][2], a[mt][3], ad);
            }
#pragma unroll
            for (int p = 0; p < 4; p++) {
                u32 bd = base + 10240u + bOff + (u32)(p * 16 * 80) + kb;
                u32 r0, r1, r2, r3;
                ldsm4(r0, r1, r2, r3, bd);
                bw[2 * p][0] = r0; bw[2 * p][1] = r1;
                bw[2 * p + 1][0] = r2; bw[2 * p + 1][1] = r3;
            }
#pragma unroll
            for (int mt = 0; mt < 2; mt++)
#pragma unroll
                for (int nt = 0; nt < 8; nt++)
                    mma16816h(acc[mt][nt], a[mt], bw[nt]);
        }
        __syncthreads();
    }

    // ---- epilogue ----
    const int tsel = (MODE == 0) ? (n0 / 768) : 0;
#pragma unroll
    for (int mt = 0; mt < 2; mt++) {
        const int m_g = m0 + wyy * 32 + mt * 16 + (lane >> 2);
        if (MODE == 0) {
            const int bq = m_g >> 12, ptok = m_g & 4095;
            const int wnd = ptok >> 8, rr = ptok & 255;
#pragma unroll
            for (int nt = 0; nt < 8; nt++) {
                const int ncol = n0 + wx * 64 + nt * 8;
                const int rem = ncol - tsel * 768;
                const int h = rem >> 6;
                const int d = (rem & 63) + 2 * (lane & 3);
                size_t rowbase = (((size_t)bq * 16 + wnd) * 12 + h) * 256;
                size_t i0 = (rowbase + rr) * 64 + d;
                size_t i1 = (rowbase + rr + 8) * 64 + d;
                float v0 = acc[mt][nt][0], v1 = acc[mt][nt][1];
                float v2 = acc[mt][nt][2], v3 = acc[mt][nt][3];
                if (tsel == 0) {
                    // Q: fold SCALE, single fp16
                    *(u32*)&g_q[i0] = pkh2(v0 * SCALE, v1 * SCALE);
                    *(u32*)&g_q[i1] = pkh2(v2 * SCALE, v3 * SCALE);
                } else {
                    __half* ph = (tsel == 1) ? g_kh : g_vh;
                    __half* pl = (tsel == 1) ? g_kl : g_vl;
                    float h0 = __half2float(__float2half(v0));
                    float h1 = __half2float(__float2half(v1));
                    float h2 = __half2float(__float2half(v2));
                    float h3 = __half2float(__float2half(v3));
                    *(u32*)&ph[i0] = pkh2(h0, h1);
                    *(u32*)&pl[i0] = pkh2(v0 - h0, v1 - h1);
                    *(u32*)&ph[i1] = pkh2(h2, h3);
                    *(u32*)&pl[i1] = pkh2(v2 - h2, v3 - h3);
                }
            }
        } else {
#pragma unroll
            for (int nt = 0; nt < 8; nt++) {
                const int ncol = n0 + wx * 64 + nt * 8 + 2 * (lane & 3);
                const float b0 = bias[ncol], b1 = bias[ncol + 1];
                *(float2*)(Cout + (size_t)m_g * 768 + ncol) =
                    make_float2(acc[mt][nt][0] + b0, acc[mt][nt][1] + b1);
                *(float2*)(Cout + (size_t)(m_g + 8) * 768 + ncol) =
                    make_float2(acc[mt][nt][2] + b0, acc[mt][nt][3] + b1);
            }
        }
    }
#undef LOAD_TILE
}

// ---------------- flash attention, fp16 asymmetric 2-term (R13 verbatim) ----------------
// one block per (b, window, head); 8 warps x 32 query rows; key chunks of 64.
// smem: 5 planes (Q, Kh, Kl, Vh, Vl), 256 rows x 72 halves (144B stride) = 36864B each.
#define AT_PL   36864
#define AT_SMEM (5 * AT_PL)      // 184320

__global__ __launch_bounds__(256, 1)
void attn_mma()
{
    extern __shared__ char smem[];
    const u32 sb = smem_u32(smem);

    const int tid = threadIdx.x;
    const int lane = tid & 31, wid = tid >> 5;
    const int blk = blockIdx.x;
    const int h = blk % NHEAD;
    const int t2 = blk / NHEAD;
    const int wnd = t2 % NWIN;
    const int b = t2 / NWIN;

    // ---- load 5 planes into padded smem ----
    {
        const size_t blkoff = (((size_t)b * NWIN + wnd) * NHEAD + h) * (WTOK * HDIM);
        const __half* srcs[5] = {g_q + blkoff, g_kh + blkoff, g_kl + blkoff,
                                 g_vh + blkoff, g_vl + blkoff};
#pragma unroll
        for (int p5 = 0; p5 < 5; p5++) {
            const __half* src = srcs[p5];
#pragma unroll
            for (int i = 0; i < 8; i++) {
                int seg = i * 256 + tid;          // 0..2047
                int row = seg >> 3, sc = seg & 7;
                uint4 v = ((const uint4*)(src + row * 64))[sc];
                *(uint4*)(smem + (size_t)p5 * AT_PL + row * 144 + sc * 16) = v;
            }
        }
    }
    __syncthreads();

    float out[2][8][4];
#pragma unroll
    for (int mt = 0; mt < 2; mt++)
#pragma unroll
        for (int nt = 0; nt < 8; nt++)
#pragma unroll
            for (int j = 0; j < 4; j++) out[mt][nt][j] = 0.f;
    float mrun[2][2] = {{-1e30f, -1e30f}, {-1e30f, -1e30f}};
    float lrun[2][2] = {{0.f, 0.f}, {0.f, 0.f}};

    const u32 qrow_base = (u32)(wid * 32 + (lane & 15));
    const u32 qcol = (u32)((lane >> 4) * 16);
    const u32 krow_off = (u32)(((lane >> 4) << 3) + (lane & 7));
    const u32 kcol = (u32)(((lane >> 3) & 1) * 16);
    const u32 vrow_off = (u32)(lane & 15);
    const u32 vcol = (u32)((lane >> 4) * 16);

    for (int jc = 0; jc < 4; jc++) {
        // ---- S = Q*Kh' + Q*Kl'  (SCALE folded into Q) ----
        float s[2][8][4];
#pragma unroll
        for (int mt = 0; mt < 2; mt++)
#pragma unroll
            for (int nt = 0; nt < 8; nt++)
#pragma unroll
                for (int j = 0; j < 4; j++) s[mt][nt][j] = 0.f;

#pragma unroll
        for (int ks = 0; ks < 4; ks++) {
            u32 qa[2][4];
#pragma unroll
            for (int mt = 0; mt < 2; mt++) {
                u32 ad = sb + (qrow_base + mt * 16) * 144 + qcol + ks * 32;
                ldsm4(qa[mt][0], qa[mt][1], qa[mt][2], qa[mt][3], ad);
            }
            u32 kh[8][2], kl[8][2];
#pragma unroll
            for (int p = 0; p < 4; p++) {
                u32 row = (u32)(jc * 64 + p * 16) + krow_off;
                u32 bd = sb + AT_PL + row * 144 + kcol + ks * 32;
                u32 r0, r1, r2, r3;
                ldsm4(r0, r1, r2, r3, bd);
                kh[2 * p][0] = r0; kh[2 * p][1] = r1;
                kh[2 * p + 1][0] = r2; kh[2 * p + 1][1] = r3;
                ldsm4(r0, r1, r2, r3, bd + AT_PL);
                kl[2 * p][0] = r0; kl[2 * p][1] = r1;
                kl[2 * p + 1][0] = r2; kl[2 * p + 1][1] = r3;
            }
#pragma unroll
            for (int mt = 0; mt < 2; mt++)
#pragma unroll
                for (int nt = 0; nt < 8; nt++) {
                    mma16816h(s[mt][nt], qa[mt], kh[nt]);
                    mma16816h(s[mt][nt], qa[mt], kl[nt]);
                }
        }

        // ---- online softmax ----
#pragma unroll
        for (int mt = 0; mt < 2; mt++) {
            float mx0 = -1e30f, mx1 = -1e30f;
#pragma unroll
            for (int nt = 0; nt < 8; nt++) {
                mx0 = fmaxf(mx0, fmaxf(s[mt][nt][0], s[mt][nt][1]));
                mx1 = fmaxf(mx1, fmaxf(s[mt][nt][2], s[mt][nt][3]));
            }
            mx0 = fmaxf(mx0, __shfl_xor_sync(0xffffffffu, mx0, 1));
            mx0 = fmaxf(mx0, __shfl_xor_sync(0xffffffffu, mx0, 2));
            mx1 = fmaxf(mx1, __shfl_xor_sync(0xffffffffu, mx1, 1));
            mx1 = fmaxf(mx1, __shfl_xor_sync(0xffffffffu, mx1, 2));
            const float mn0 = fmaxf(mrun[mt][0], mx0);
            const float mn1 = fmaxf(mrun[mt][1], mx1);
            const float c0 = __expf(mrun[mt][0] - mn0);
            const float c1 = __expf(mrun[mt][1] - mn1);
            mrun[mt][0] = mn0; mrun[mt][1] = mn1;
            lrun[mt][0] *= c0; lrun[mt][1] *= c1;
#pragma unroll
            for (int nt = 0; nt < 8; nt++) {
                out[mt][nt][0] *= c0; out[mt][nt][1] *= c0;
                out[mt][nt][2] *= c1; out[mt][nt][3] *= c1;
            }
            float sum0 = 0.f, sum1 = 0.f;
#pragma unroll
            for (int nt = 0; nt < 8; nt++) {
                float p0 = __expf(s[mt][nt][0] - mn0);
                float p1 = __expf(s[mt][nt][1] - mn0);
                float p2 = __expf(s[mt][nt][2] - mn1);
                float p3 = __expf(s[mt][nt][3] - mn1);
                s[mt][nt][0] = p0; s[mt][nt][1] = p1;
                s[mt][nt][2] = p2; s[mt][nt][3] = p3;
                sum0 += p0 + p1; sum1 += p2 + p3;
            }
            sum0 += __shfl_xor_sync(0xffffffffu, sum0, 1);
            sum0 += __shfl_xor_sync(0xffffffffu, sum0, 2);
            sum1 += __shfl_xor_sync(0xffffffffu, sum1, 1);
            sum1 += __shfl_xor_sync(0xffffffffu, sum1, 2);
            lrun[mt][0] += sum0; lrun[mt][1] += sum1;
        }

        // ---- O += P*(Vh + Vl), P single fp16 ----
#pragma unroll
        for (int ks = 0; ks < 4; ks++) {
            u32 pa[2][4];
#pragma unroll
            for (int mt = 0; mt < 2; mt++) {
#pragma unroll
                for (int half = 0; half < 2; half++) {
                    const float* sv = s[mt][2 * ks + half];
                    pa[mt][0 + 2 * half] = pkh2(sv[0], sv[1]);
                    pa[mt][1 + 2 * half] = pkh2(sv[2], sv[3]);
                }
            }
            u32 vh[8][2], vl[8][2];
#pragma unroll
            for (int p = 0; p < 4; p++) {
                u32 row = (u32)(jc * 64 + ks * 16) + vrow_off;
                u32 vd = sb + 3 * AT_PL + row * 144 + vcol + p * 32;
                u32 r0, r1, r2, r3;
                ldsm4t(r0, r1, r2, r3, vd);
                vh[2 * p][0] = r0; vh[2 * p][1] = r1;
                vh[2 * p + 1][0] = r2; vh[2 * p + 1][1] = r3;
                ldsm4t(r0, r1, r2, r3, vd + AT_PL);
                vl[2 * p][0] = r0; vl[2 * p][1] = r1;
                vl[2 * p + 1][0] = r2; vl[2 * p + 1][1] = r3;
            }
#pragma unroll
            for (int mt = 0; mt < 2; mt++)
#pragma unroll
                for (int nt = 0; nt < 8; nt++) {
                    mma16816h(out[mt][nt], pa[mt], vh[nt]);
                    mma16816h(out[mt][nt], pa[mt], vl[nt]);
                }
        }
    }

    // ---- epilogue: scale by 1/l, inverse-perm scatter, write y single fp16 ----
#pragma unroll
    for (int mt = 0; mt < 2; mt++) {
        const float inv0 = 1.f / lrun[mt][0];
        const float inv1 = 1.f / lrun[mt][1];
#pragma unroll
        for (int half = 0; half < 2; half++) {
            const int row = wid * 32 + mt * 16 + (lane >> 2) + half * 8;
            const int n = perm_tok(wnd * WTOK + row);
            const size_t base = ((size_t)(b * NTOK + n)) * CCH + h * HDIM;
            const float inv = half ? inv1 : inv0;
#pragma unroll
            for (int nt = 0; nt < 8; nt++) {
                const int col = nt * 8 + 2 * (lane & 3);
                float v0 = out[mt][nt][2 * half] * inv;
                float v1 = out[mt][nt][2 * half + 1] * inv;
                *(u32*)&g_y[base + col] = pkh2(v0, v1);
            }
        }
    }
}

// ---------------- launch ----------------
extern "C" void kernel_launch(void* const* d_in, const int* in_sizes, int n_in,
                              void* d_out, int out_size)
{
    const float* x      = (const float*)d_in[0];
    const float* qkv_w  = (const float*)d_in[1];
    const float* proj_w = (const float*)d_in[2];
    const float* proj_b = (const float*)d_in[3];
    float* out = (float*)d_out;

    cudaFuncSetAttribute(attn_mma, cudaFuncAttributeMaxDynamicSharedMemorySize, AT_SMEM);
    cudaFuncSetAttribute(gemm_mma<0>, cudaFuncAttributeMaxDynamicSharedMemorySize, GM_SMEM);
    cudaFuncSetAttribute(gemm_mma<1>, cudaFuncAttributeMaxDynamicSharedMemorySize, GM_SMEM);

    convert_x<<<MTOT, 192>>>(x);
    convert_w<<<3072, 192>>>(qkv_w, proj_w);

    // QKV: M=32768 x N=2304 -> (12, 256)
    gemm_mma<0><<<dim3(12, 256), 384, GM_SMEM>>>(nullptr, nullptr);

    attn_mma<<<BATCH * NWIN * NHEAD, 256, AT_SMEM>>>();

    // proj: M=32768 x N=768 -> (4, 256)
    gemm_mma<1><<<dim3(4, 256), 384, GM_SMEM>>>(proj_b, out);
}

// round 17
// speedup vs baseline: 1.6707x; 1.1852x over previous
#include <cuda_runtime.h>
#include <cuda_fp16.h>

// ---------------- problem constants ----------------
#define BATCH 8
#define NTOK  4096
#define CCH   768
#define NHEAD 12
#define HDIM  64
#define NWIN  16
#define WTOK  256
#define K_DIM 768
#define SCALE 0.125f
#define MTOT  (BATCH * NTOK)     // 32768
#define PL3   (BATCH * NWIN * NHEAD * WTOK * HDIM)   // 25,165,824

typedef unsigned long long ull;
typedef unsigned int u32;

// ---------------- device scratch (fp16 planes) ----------------
__device__ __half g_q[PL3];                  // Q, SCALE pre-folded, single fp16
__device__ __half g_kh[PL3], g_kl[PL3];      // K hi/lo
__device__ __half g_vh[PL3], g_vl[PL3];      // V hi/lo
__device__ __half g_x[(size_t)MTOT * K_DIM]; // permuted x, single fp16
__device__ __half g_y[(size_t)MTOT * K_DIM]; // attn out (orig order), single fp16
__device__ __half g_wq[2304 * 768];          // qkv weights, single fp16
__device__ __half g_wp[768 * 768];           // proj weights, single fp16

// ---------------- helpers ----------------
__device__ __forceinline__ int perm_tok(int p) {
    int wnd = p >> 8, r = p & 255;
    int wr = wnd >> 2, wc = wnd & 3;
    int i = r >> 4, j = r & 15;
    return ((wr << 4) + i) * 64 + (wc << 4) + j;
}
__device__ __forceinline__ u32 smem_u32(const void* p) {
    u32 a;
    asm("{ .reg .u64 t; cvta.to.shared.u64 t, %1; cvt.u32.u64 %0, t; }" : "=r"(a) : "l"(p));
    return a;
}
__device__ __forceinline__ void ldsm4(u32& r0, u32& r1, u32& r2, u32& r3, u32 addr) {
    asm volatile("ldmatrix.sync.aligned.m8n8.x4.shared.b16 {%0,%1,%2,%3}, [%4];"
                 : "=r"(r0), "=r"(r1), "=r"(r2), "=r"(r3) : "r"(addr));
}
__device__ __forceinline__ void ldsm4t(u32& r0, u32& r1, u32& r2, u32& r3, u32 addr) {
    asm volatile("ldmatrix.sync.aligned.m8n8.x4.trans.shared.b16 {%0,%1,%2,%3}, [%4];"
                 : "=r"(r0), "=r"(r1), "=r"(r2), "=r"(r3) : "r"(addr));
}
__device__ __forceinline__ void mma16816h(float* c, const u32* a, const u32* b) {
    asm volatile("mma.sync.aligned.m16n8k16.row.col.f32.f16.f16.f32 "
                 "{%0,%1,%2,%3}, {%4,%5,%6,%7}, {%8,%9}, {%0,%1,%2,%3};"
                 : "+f"(c[0]), "+f"(c[1]), "+f"(c[2]), "+f"(c[3])
                 : "r"(a[0]), "r"(a[1]), "r"(a[2]), "r"(a[3]), "r"(b[0]), "r"(b[1]));
}
__device__ __forceinline__ void cpasync16(u32 saddr, const void* g) {
    asm volatile("cp.async.cg.shared.global [%0], [%1], 16;" :: "r"(saddr), "l"(g) : "memory");
}
#define CP_COMMIT()  asm volatile("cp.async.commit_group;" ::: "memory")
#define CP_WAIT(n)   asm volatile("cp.async.wait_group %0;" :: "n"(n) : "memory")

// pack two f32 -> f16x2 (element0 = x0)
__device__ __forceinline__ u32 pkh2(float x0, float x1) {
    u32 r;
    asm("cvt.rn.f16x2.f32 %0, %2, %1;" : "=r"(r) : "f"(x0), "f"(x1));
    return r;
}

// ---------------- convert kernels ----------------
__global__ __launch_bounds__(192) void convert_x(const float* __restrict__ x)
{
    const int m = blockIdx.x;
    const int t = threadIdx.x;
    const int b = m >> 12, p = m & 4095;
    const float4* src = (const float4*)(x + (size_t)((b << 12) + perm_tok(p)) * K_DIM);
    float4 v = src[t];
    ull packed = (ull)pkh2(v.x, v.y) | ((ull)pkh2(v.z, v.w) << 32);
    *(ull*)&g_x[(size_t)m * K_DIM + t * 4] = packed;
}

__global__ __launch_bounds__(192) void convert_w(const float* __restrict__ qkv_w,
                                                 const float* __restrict__ proj_w)
{
    const int row = blockIdx.x;
    const int t = threadIdx.x;
    const float* src;
    __half* dh;
    if (row < 2304) {
        src = qkv_w + (size_t)row * 768;
        dh = g_wq + (size_t)row * 768;
    } else {
        int r2 = row - 2304;
        src = proj_w + (size_t)r2 * 768;
        dh = g_wp + (size_t)r2 * 768;
    }
    float4 v = ((const float4*)src)[t];
    *(ull*)&dh[t * 4] = (ull)pkh2(v.x, v.y) | ((ull)pkh2(v.z, v.w) << 32);
}

// ---------------- mma.sync fp16 single-term GEMM ----------------
// C[m][n] = sum_k A[m][k]*W[n][k], both single fp16, fp32 accum.
// CTA 128x128, BK=64 (two 32-half sub-tiles), 8 warps (4x2), warp tile 32x64,
// double-buffered cp.async, 2 CTAs/SM.
// buffer: sub0{A 10240 | W 10240} sub1{A | W} = 40960; x2 bufs = 81920.
#define GM_SMEM 81920

template <int MODE>
__global__ __launch_bounds__(256, 2)
void gemm_mma(const float* __restrict__ bias, float* __restrict__ Cout)
{
    extern __shared__ char smem[];
    const __half* Ap0 = (MODE == 0) ? g_x : g_y;
    const __half* Wp0 = (MODE == 0) ? g_wq : g_wp;

    const int tid = threadIdx.x;
    const int lane = tid & 31, wid = tid >> 5;
    const int wy = wid >> 1, wx = wid & 1;       // 4x2 warp grid
    const int m0 = blockIdx.y * 128;
    const int n0 = blockIdx.x * 128;
    const u32 sb = smem_u32(smem);

    const __half* Ahp = Ap0 + (size_t)m0 * 768;
    const __half* Whp = Wp0 + (size_t)n0 * 768;

    float acc[2][8][4];
#pragma unroll
    for (int mt = 0; mt < 2; mt++)
#pragma unroll
        for (int nt = 0; nt < 8; nt++)
#pragma unroll
            for (int j = 0; j < 4; j++) acc[mt][nt][j] = 0.f;

    const u32 aOff = (u32)((wy * 32 + (lane & 15)) * 80 + ((lane >> 4) * 16));
    const u32 bOff = (u32)((wx * 64 + ((lane >> 4) << 3) + (lane & 7)) * 80
                           + (((lane >> 3) & 1) * 16));

    // loader: 2048 16B segments per BK=64 chunk (A 1024, W 1024, two sub-tiles)
#define LOAD_TILE(c, buf) do {                                                    \
    u32 dbase = sb + (u32)(buf) * 40960u;                                         \
    int kk = (c) * 64;                                                            \
    _Pragma("unroll")                                                             \
    for (int i = 0; i < 8; i++) {                                                 \
        int idx = tid + i * 256;              /* 0..2047 */                       \
        int sub = idx >> 10;                  /* 0,1 */                           \
        int j = idx & 1023;                                                       \
        int row = (j & 511) >> 2, q = j & 3;                                      \
        u32 dsub = dbase + (u32)sub * 20480u + ((j < 512) ? 0u : 10240u);         \
        const __half* gp = (j < 512) ? Ahp : Whp;                                 \
        cpasync16(dsub + (u32)(row * 80 + q * 16),                                \
                  gp + (size_t)row * 768 + kk + sub * 32 + q * 8);                \
    }                                                                             \
} while (0)

    LOAD_TILE(0, 0);
    CP_COMMIT();

    for (int c = 0; c < 12; c++) {
        const int buf = c & 1;
        if (c + 1 < 12) {
            LOAD_TILE(c + 1, buf ^ 1);
            CP_COMMIT();
            CP_WAIT(1);
        } else {
            CP_WAIT(0);
        }
        __syncthreads();

        const u32 base = sb + (u32)buf * 40960u;
#pragma unroll
        for (int sub = 0; sub < 2; sub++) {
            const u32 base2 = base + (u32)sub * 20480u;
#pragma unroll
            for (int ks = 0; ks < 2; ks++) {
                const u32 kb = (u32)(ks * 32);
                u32 a[2][4], bw[8][2];
#pragma unroll
                for (int mt = 0; mt < 2; mt++) {
                    u32 ad = base2 + aOff + (u32)(mt * 16 * 80) + kb;
                    ldsm4(a[mt][0], a[mt][1], a[mt][2], a[mt][3], ad);
                }
#pragma unroll
                for (int p = 0; p < 4; p++) {
                    u32 bd = base2 + 10240u + bOff + (u32)(p * 16 * 80) + kb;
                    u32 r0, r1, r2, r3;
                    ldsm4(r0, r1, r2, r3, bd);
                    bw[2 * p][0] = r0; bw[2 * p][1] = r1;
                    bw[2 * p + 1][0] = r2; bw[2 * p + 1][1] = r3;
                }
#pragma unroll
                for (int mt = 0; mt < 2; mt++)
#pragma unroll
                    for (int nt = 0; nt < 8; nt++)
                        mma16816h(acc[mt][nt], a[mt], bw[nt]);
            }
        }
        __syncthreads();
    }

    // ---- epilogue ----
    const int tsel = (MODE == 0) ? (n0 / 768) : 0;
#pragma unroll
    for (int mt = 0; mt < 2; mt++) {
        const int m_g = m0 + wy * 32 + mt * 16 + (lane >> 2);
        if (MODE == 0) {
            const int bq = m_g >> 12, ptok = m_g & 4095;
            const int wnd = ptok >> 8, rr = ptok & 255;
#pragma unroll
            for (int nt = 0; nt < 8; nt++) {
                const int ncol = n0 + wx * 64 + nt * 8;
                const int rem = ncol - tsel * 768;
                const int h = rem >> 6;
                const int d = (rem & 63) + 2 * (lane & 3);
                size_t rowbase = (((size_t)bq * 16 + wnd) * 12 + h) * 256;
                size_t i0 = (rowbase + rr) * 64 + d;
                size_t i1 = (rowbase + rr + 8) * 64 + d;
                float v0 = acc[mt][nt][0], v1 = acc[mt][nt][1];
                float v2 = acc[mt][nt][2], v3 = acc[mt][nt][3];
                if (tsel == 0) {
                    *(u32*)&g_q[i0] = pkh2(v0 * SCALE, v1 * SCALE);
                    *(u32*)&g_q[i1] = pkh2(v2 * SCALE, v3 * SCALE);
                } else {
                    __half* ph = (tsel == 1) ? g_kh : g_vh;
                    __half* pl = (tsel == 1) ? g_kl : g_vl;
                    float h0 = __half2float(__float2half(v0));
                    float h1 = __half2float(__float2half(v1));
                    float h2 = __half2float(__float2half(v2));
                    float h3 = __half2float(__float2half(v3));
                    *(u32*)&ph[i0] = pkh2(h0, h1);
                    *(u32*)&pl[i0] = pkh2(v0 - h0, v1 - h1);
                    *(u32*)&ph[i1] = pkh2(h2, h3);
                    *(u32*)&pl[i1] = pkh2(v2 - h2, v3 - h3);
                }
            }
        } else {
#pragma unroll
            for (int nt = 0; nt < 8; nt++) {
                const int ncol = n0 + wx * 64 + nt * 8 + 2 * (lane & 3);
                const float b0 = bias[ncol], b1 = bias[ncol + 1];
                *(float2*)(Cout + (size_t)m_g * 768 + ncol) =
                    make_float2(acc[mt][nt][0] + b0, acc[mt][nt][1] + b1);
                *(float2*)(Cout + (size_t)(m_g + 8) * 768 + ncol) =
                    make_float2(acc[mt][nt][2] + b0, acc[mt][nt][3] + b1);
            }
        }
    }
#undef LOAD_TILE
}

// ---------------- flash attention, fp16 asymmetric 2-term (R15 verbatim) ----------------
// one block per (b, window, head); 8 warps x 32 query rows; key chunks of 64.
// smem: 5 planes (Q, Kh, Kl, Vh, Vl), 256 rows x 72 halves (144B stride) = 36864B each.
#define AT_PL   36864
#define AT_SMEM (5 * AT_PL)      // 184320

__global__ __launch_bounds__(256, 1)
void attn_mma()
{
    extern __shared__ char smem[];
    const u32 sb = smem_u32(smem);

    const int tid = threadIdx.x;
    const int lane = tid & 31, wid = tid >> 5;
    const int blk = blockIdx.x;
    const int h = blk % NHEAD;
    const int t2 = blk / NHEAD;
    const int wnd = t2 % NWIN;
    const int b = t2 / NWIN;

    // ---- load 5 planes into padded smem ----
    {
        const size_t blkoff = (((size_t)b * NWIN + wnd) * NHEAD + h) * (WTOK * HDIM);
        const __half* srcs[5] = {g_q + blkoff, g_kh + blkoff, g_kl + blkoff,
                                 g_vh + blkoff, g_vl + blkoff};
#pragma unroll
        for (int p5 = 0; p5 < 5; p5++) {
            const __half* src = srcs[p5];
#pragma unroll
            for (int i = 0; i < 8; i++) {
                int seg = i * 256 + tid;          // 0..2047
                int row = seg >> 3, sc = seg & 7;
                uint4 v = ((const uint4*)(src + row * 64))[sc];
                *(uint4*)(smem + (size_t)p5 * AT_PL + row * 144 + sc * 16) = v;
            }
        }
    }
    __syncthreads();

    float out[2][8][4];
#pragma unroll
    for (int mt = 0; mt < 2; mt++)
#pragma unroll
        for (int nt = 0; nt < 8; nt++)
#pragma unroll
            for (int j = 0; j < 4; j++) out[mt][nt][j] = 0.f;
    float mrun[2][2] = {{-1e30f, -1e30f}, {-1e30f, -1e30f}};
    float lrun[2][2] = {{0.f, 0.f}, {0.f, 0.f}};

    const u32 qrow_base = (u32)(wid * 32 + (lane & 15));
    const u32 qcol = (u32)((lane >> 4) * 16);
    const u32 krow_off = (u32)(((lane >> 4) << 3) + (lane & 7));
    const u32 kcol = (u32)(((lane >> 3) & 1) * 16);
    const u32 vrow_off = (u32)(lane & 15);
    const u32 vcol = (u32)((lane >> 4) * 16);

    for (int jc = 0; jc < 4; jc++) {
        // ---- S = Q*Kh' + Q*Kl'  (SCALE folded into Q) ----
        float s[2][8][4];
#pragma unroll
        for (int mt = 0; mt < 2; mt++)
#pragma unroll
            for (int nt = 0; nt < 8; nt++)
#pragma unroll
                for (int j = 0; j < 4; j++) s[mt][nt][j] = 0.f;

#pragma unroll
        for (int ks = 0; ks < 4; ks++) {
            u32 qa[2][4];
#pragma unroll
            for (int mt = 0; mt < 2; mt++) {
                u32 ad = sb + (qrow_base + mt * 16) * 144 + qcol + ks * 32;
                ldsm4(qa[mt][0], qa[mt][1], qa[mt][2], qa[mt][3], ad);
            }
            u32 kh[8][2], kl[8][2];
#pragma unroll
            for (int p = 0; p < 4; p++) {
                u32 row = (u32)(jc * 64 + p * 16) + krow_off;
                u32 bd = sb + AT_PL + row * 144 + kcol + ks * 32;
                u32 r0, r1, r2, r3;
                ldsm4(r0, r1, r2, r3, bd);
                kh[2 * p][0] = r0; kh[2 * p][1] = r1;
                kh[2 * p + 1][0] = r2; kh[2 * p + 1][1] = r3;
                ldsm4(r0, r1, r2, r3, bd + AT_PL);
                kl[2 * p][0] = r0; kl[2 * p][1] = r1;
                kl[2 * p + 1][0] = r2; kl[2 * p + 1][1] = r3;
            }
#pragma unroll
            for (int mt = 0; mt < 2; mt++)
#pragma unroll
                for (int nt = 0; nt < 8; nt++) {
                    mma16816h(s[mt][nt], qa[mt], kh[nt]);
                    mma16816h(s[mt][nt], qa[mt], kl[nt]);
                }
        }

        // ---- online softmax ----
#pragma unroll
        for (int mt = 0; mt < 2; mt++) {
            float mx0 = -1e30f, mx1 = -1e30f;
#pragma unroll
            for (int nt = 0; nt < 8; nt++) {
                mx0 = fmaxf(mx0, fmaxf(s[mt][nt][0], s[mt][nt][1]));
                mx1 = fmaxf(mx1, fmaxf(s[mt][nt][2], s[mt][nt][3]));
            }
            mx0 = fmaxf(mx0, __shfl_xor_sync(0xffffffffu, mx0, 1));
            mx0 = fmaxf(mx0, __shfl_xor_sync(0xffffffffu, mx0, 2));
            mx1 = fmaxf(mx1, __shfl_xor_sync(0xffffffffu, mx1, 1));
            mx1 = fmaxf(mx1, __shfl_xor_sync(0xffffffffu, mx1, 2));
            const float mn0 = fmaxf(mrun[mt][0], mx0);
            const float mn1 = fmaxf(mrun[mt][1], mx1);
            const float c0 = __expf(mrun[mt][0] - mn0);
            const float c1 = __expf(mrun[mt][1] - mn1);
            mrun[mt][0] = mn0; mrun[mt][1] = mn1;
            lrun[mt][0] *= c0; lrun[mt][1] *= c1;
#pragma unroll
            for (int nt = 0; nt < 8; nt++) {
                out[mt][nt][0] *= c0; out[mt][nt][1] *= c0;
                out[mt][nt][2] *= c1; out[mt][nt][3] *= c1;
            }
            float sum0 = 0.f, sum1 = 0.f;
#pragma unroll
            for (int nt = 0; nt < 8; nt++) {
                float p0 = __expf(s[mt][nt][0] - mn0);
                float p1 = __expf(s[mt][nt][1] - mn0);
                float p2 = __expf(s[mt][nt][2] - mn1);
                float p3 = __expf(s[mt][nt][3] - mn1);
                s[mt][nt][0] = p0; s[mt][nt][1] = p1;
                s[mt][nt][2] = p2; s[mt][nt][3] = p3;
                sum0 += p0 + p1; sum1 += p2 + p3;
            }
            sum0 += __shfl_xor_sync(0xffffffffu, sum0, 1);
            sum0 += __shfl_xor_sync(0xffffffffu, sum0, 2);
            sum1 += __shfl_xor_sync(0xffffffffu, sum1, 1);
            sum1 += __shfl_xor_sync(0xffffffffu, sum1, 2);
            lrun[mt][0] += sum0; lrun[mt][1] += sum1;
        }

        // ---- O += P*(Vh + Vl), P single fp16 ----
#pragma unroll
        for (int ks = 0; ks < 4; ks++) {
            u32 pa[2][4];
#pragma unroll
            for (int mt = 0; mt < 2; mt++) {
#pragma unroll
                for (int half = 0; half < 2; half++) {
                    const float* sv = s[mt][2 * ks + half];
                    pa[mt][0 + 2 * half] = pkh2(sv[0], sv[1]);
                    pa[mt][1 + 2 * half] = pkh2(sv[2], sv[3]);
                }
            }
            u32 vh[8][2], vl[8][2];
#pragma unroll
            for (int p = 0; p < 4; p++) {
                u32 row = (u32)(jc * 64 + ks * 16) + vrow_off;
                u32 vd = sb + 3 * AT_PL + row * 144 + vcol + p * 32;
                u32 r0, r1, r2, r3;
                ldsm4t(r0, r1, r2, r3, vd);
                vh[2 * p][0] = r0; vh[2 * p][1] = r1;
                vh[2 * p + 1][0] = r2; vh[2 * p + 1][1] = r3;
                ldsm4t(r0, r1, r2, r3, vd + AT_PL);
                vl[2 * p][0] = r0; vl[2 * p][1] = r1;
                vl[2 * p + 1][0] = r2; vl[2 * p + 1][1] = r3;
            }
#pragma unroll
            for (int mt = 0; mt < 2; mt++)
#pragma unroll
                for (int nt = 0; nt < 8; nt++) {
                    mma16816h(out[mt][nt], pa[mt], vh[nt]);
                    mma16816h(out[mt][nt], pa[mt], vl[nt]);
                }
        }
    }

    // ---- epilogue: scale by 1/l, inverse-perm scatter, write y single fp16 ----
#pragma unroll
    for (int mt = 0; mt < 2; mt++) {
        const float inv0 = 1.f / lrun[mt][0];
        const float inv1 = 1.f / lrun[mt][1];
#pragma unroll
        for (int half = 0; half < 2; half++) {
            const int row = wid * 32 + mt * 16 + (lane >> 2) + half * 8;
            const int n = perm_tok(wnd * WTOK + row);
            const size_t base = ((size_t)(b * NTOK + n)) * CCH + h * HDIM;
            const float inv = half ? inv1 : inv0;
#pragma unroll
            for (int nt = 0; nt < 8; nt++) {
                const int col = nt * 8 + 2 * (lane & 3);
                float v0 = out[mt][nt][2 * half] * inv;
                float v1 = out[mt][nt][2 * half + 1] * inv;
                *(u32*)&g_y[base + col] = pkh2(v0, v1);
            }
        }
    }
}

// ---------------- launch ----------------
extern "C" void kernel_launch(void* const* d_in, const int* in_sizes, int n_in,
                              void* d_out, int out_size)
{
    const float* x      = (const float*)d_in[0];
    const float* qkv_w  = (const float*)d_in[1];
    const float* proj_w = (const float*)d_in[2];
    const float* proj_b = (const float*)d_in[3];
    float* out = (float*)d_out;

    cudaFuncSetAttribute(attn_mma, cudaFuncAttributeMaxDynamicSharedMemorySize, AT_SMEM);
    cudaFuncSetAttribute(gemm_mma<0>, cudaFuncAttributeMaxDynamicSharedMemorySize, GM_SMEM);
    cudaFuncSetAttribute(gemm_mma<1>, cudaFuncAttributeMaxDynamicSharedMemorySize, GM_SMEM);

    convert_x<<<MTOT, 192>>>(x);
    convert_w<<<3072, 192>>>(qkv_w, proj_w);

    // QKV: M=32768 x N=2304 -> (18, 256)
    gemm_mma<0><<<dim3(18, 256), 256, GM_SMEM>>>(nullptr, nullptr);

    attn_mma<<<BATCH * NWIN * NHEAD, 256, AT_SMEM>>>();

    // proj: M=32768 x N=768 -> (6, 256)
    gemm_mma<1><<<dim3(6, 256), 256, GM_SMEM>>>(proj_b, out);
}